// round 10
// baseline (speedup 1.0000x reference)
#include <cuda_runtime.h>
#include <cuda_bf16.h>
#include <cuda_fp16.h>
#include <cstdint>

#define N_NODES 100000
#define D 128

// ---------------- scratch (device globals: no allocations allowed) ----------
__device__ int    g_rowptr[N_NODES + 1];
__device__ __half g_hW[(size_t)N_NODES * D];   // h @ W.T in fp16, 25.6 MB
// Pre-swizzled W fragments for mma.sync m16n8k16 fp16.
// Index: ((kstep*16 + ntile)*32 + lane) -> uint2 {b0, b1}
__device__ uint2 g_Whf[8 * 16 * 32];

// ---------------- Kernel 1: row_ptr via scatter over sorted rows ------------
__global__ void rowptr_kernel(const int* __restrict__ rows, int n_edges) {
    int e = blockIdx.x * blockDim.x + threadIdx.x;
    if (e >= n_edges) return;
    int b = __ldg(&rows[e]);
    if (e == 0) {
        for (int i = 0; i <= b; i++) g_rowptr[i] = 0;
    } else {
        int a = __ldg(&rows[e - 1]);
        for (int i = a + 1; i <= b; i++) g_rowptr[i] = e;
    }
    if (e == n_edges - 1) {
        for (int i = b + 1; i <= N_NODES; i++) g_rowptr[i] = n_edges;
    }
}

// ---------------- Kernel 1b: W fragment prep (fp16) -------------------------
__device__ __forceinline__ uint32_t pack2_h16(float x, float y) {
    __half2 v = __floats2half2_rn(x, y);
    return *(uint32_t*)&v;
}

__global__ void wprep_kernel(const float* __restrict__ W) {
    int t = blockIdx.x * blockDim.x + threadIdx.x;   // 0..4095
    if (t >= 8 * 16 * 32) return;
    int lane  = t & 31;
    int ntile = (t >> 5) & 15;
    int kstep = t >> 9;

    int n  = ntile * 8 + (lane >> 2);
    int k0 = kstep * 16 + (lane & 3) * 2;

    float w00 = __ldg(&W[n * 128 + k0]);
    float w01 = __ldg(&W[n * 128 + k0 + 1]);
    float w10 = __ldg(&W[n * 128 + k0 + 8]);
    float w11 = __ldg(&W[n * 128 + k0 + 9]);

    uint2 f;
    f.x = pack2_h16(w00, w01);
    f.y = pack2_h16(w10, w11);
    g_Whf[t] = f;
}

// ---------------- Kernel 2: g = h @ W.T, smem-staged fp16 mma ----------------
// Block 128 threads (4 warps), tile 64 rows x 128 cols.
// Warp w: rows (w>>1)*32 .. +32, cols (w&1)*64 .. +64 (8 n-tiles, 2 row-frags).
// A staged via coalesced LDG.128 -> fp16 smem (pad 136 halves/row:
// fragment LDS.32 banks = 4*grp + quad -> conflict-free).
// Epilogue staged back through smem -> coalesced uint4 stores.
#define MTILE 64
#define APAD  136

__device__ __forceinline__ void mma_f16(float* c, const uint32_t* a, uint2 b) {
    asm volatile(
        "mma.sync.aligned.m16n8k16.row.col.f32.f16.f16.f32 "
        "{%0,%1,%2,%3}, {%4,%5,%6,%7}, {%8,%9}, {%0,%1,%2,%3};"
        : "+f"(c[0]), "+f"(c[1]), "+f"(c[2]), "+f"(c[3])
        : "r"(a[0]), "r"(a[1]), "r"(a[2]), "r"(a[3]), "r"(b.x), "r"(b.y));
}

__global__ void __launch_bounds__(128, 4) gemm_kernel(
    const float* __restrict__ A)   // h [N_NODES, 128]
{
    __shared__ __half sA[MTILE * APAD];   // 17.4 KB

    const int tid    = threadIdx.x;
    const int lane   = tid & 31;
    const int warp   = tid >> 5;
    const int m_base = blockIdx.x * MTILE;

    // Stage A: 64 rows x 128 f32 = 2048 float4, 16 per thread, coalesced.
    #pragma unroll
    for (int q = 0; q < 16; q++) {
        int idx = q * 128 + tid;          // 0..2047
        int row = idx >> 5;               // 32 float4 per row
        int c4  = idx & 31;
        int rsrc = min(m_base + row, N_NODES - 1);
        float4 v = __ldg(&((const float4*)A)[(size_t)rsrc * 32 + c4]);
        __half2 p0 = __floats2half2_rn(v.x, v.y);
        __half2 p1 = __floats2half2_rn(v.z, v.w);
        *(__half2*)&sA[row * APAD + c4 * 4]     = p0;
        *(__half2*)&sA[row * APAD + c4 * 4 + 2] = p1;
    }
    __syncthreads();

    const int grp  = lane >> 2;           // 0..7
    const int quad = lane & 3;            // 0..3
    const int mrow = (warp >> 1) * 32;    // 0 or 32
    const int ntb  = (warp & 1) * 8;      // 0 or 8

    float acc[2][8][4];
    #pragma unroll
    for (int f = 0; f < 2; f++)
        #pragma unroll
        for (int nt = 0; nt < 8; nt++)
            #pragma unroll
            for (int i = 0; i < 4; i++) acc[f][nt][i] = 0.f;

    #pragma unroll
    for (int kstep = 0; kstep < 8; kstep++) {
        int kb = kstep * 16 + quad * 2;
        uint32_t a[2][4];
        #pragma unroll
        for (int f = 0; f < 2; f++) {
            int r = mrow + f * 16 + grp;
            a[f][0] = *(uint32_t*)&sA[r * APAD + kb];
            a[f][1] = *(uint32_t*)&sA[(r + 8) * APAD + kb];
            a[f][2] = *(uint32_t*)&sA[r * APAD + kb + 8];
            a[f][3] = *(uint32_t*)&sA[(r + 8) * APAD + kb + 8];
        }
        #pragma unroll
        for (int nt = 0; nt < 8; nt++) {
            uint2 wh = __ldg(&g_Whf[(kstep * 16 + ntb + nt) * 32 + lane]);
            mma_f16(acc[0][nt], a[0], wh);
            mma_f16(acc[1][nt], a[1], wh);
        }
    }
    __syncthreads();   // A fragments consumed; reuse sA for output staging

    // Stage results into smem as fp16.
    #pragma unroll
    for (int f = 0; f < 2; f++) {
        #pragma unroll
        for (int nt = 0; nt < 8; nt++) {
            int col = (ntb + nt) * 8 + quad * 2;
            int r0  = mrow + f * 16 + grp;
            *(__half2*)&sA[r0 * APAD + col] =
                __floats2half2_rn(acc[f][nt][0], acc[f][nt][1]);
            *(__half2*)&sA[(r0 + 8) * APAD + col] =
                __floats2half2_rn(acc[f][nt][2], acc[f][nt][3]);
        }
    }
    __syncthreads();

    // Coalesced store: 64 rows x 256B = 1024 x 16B, 8 per thread.
    #pragma unroll
    for (int q = 0; q < 8; q++) {
        int idx = q * 128 + tid;          // 0..1023
        int row = idx >> 4;
        int c16 = idx & 15;
        int rdst = m_base + row;
        if (rdst < N_NODES) {
            uint4 v = *(uint4*)&sA[row * APAD + c16 * 8];
            *(uint4*)&g_hW[(size_t)rdst * 128 + c16 * 8] = v;
        }
    }
}

// ---------------- Kernel 3: SpMM, fp16-pair inner accum, flush-4 ------------
// Warp per node; lane l owns features [4l, 4l+4) (one uint2 = 2 half2).
// Edges in groups of 4: fp16x2 hfma2 accumulation, flushed to fp32 per group.
// Zero-padded lanes (v=0) are exact no-ops in hfma2.
__global__ void __launch_bounds__(256) spmm_kernel(
    const int*   __restrict__ cols,
    const float* __restrict__ vals,
    const float* __restrict__ bias,
    float*       __restrict__ out)
{
    const int warp_id = (blockIdx.x * blockDim.x + threadIdx.x) >> 5;
    const unsigned lane = threadIdx.x & 31;
    if (warp_id >= N_NODES) return;

    const int start = g_rowptr[warp_id];
    const int end   = g_rowptr[warp_id + 1];

    const uint2* __restrict__ gl = ((const uint2*)g_hW) + lane;

    float4 acc = make_float4(0.f, 0.f, 0.f, 0.f);

    for (int e = start; e < end; e += 32) {
        int avail = min(32, end - e);
        int c = 0; float v = 0.f;
        if ((int)lane < avail) {
            c = __ldg(&cols[e + lane]);
            v = __ldg(&vals[e + lane]);
        }
        int ngroups = (avail + 3) >> 2;
        for (int g = 0; g < ngroups; g++) {
            __half2 h0 = __float2half2_rn(0.f);
            __half2 h1 = __float2half2_rn(0.f);
            #pragma unroll
            for (int j = 0; j < 4; j++) {
                unsigned cj = (unsigned)__shfl_sync(0xffffffffu, c, g * 4 + j);
                float    vj = __shfl_sync(0xffffffffu, v, g * 4 + j);
                __half2  vh = __floats2half2_rn(vj, vj);
                uint2 raw = __ldg(&gl[cj * 32u]);
                h0 = __hfma2(vh, *(__half2*)&raw.x, h0);
                h1 = __hfma2(vh, *(__half2*)&raw.y, h1);
            }
            float2 f0 = __half22float2(h0);
            float2 f1 = __half22float2(h1);
            acc.x += f0.x;  acc.y += f0.y;
            acc.z += f1.x;  acc.w += f1.y;
        }
    }

    float4 b4 = __ldg(&((const float4*)bias)[lane]);
    acc.x = fmaxf(acc.x + b4.x, 0.f);
    acc.y = fmaxf(acc.y + b4.y, 0.f);
    acc.z = fmaxf(acc.z + b4.z, 0.f);
    acc.w = fmaxf(acc.w + b4.w, 0.f);

    ((float4*)out)[(size_t)warp_id * 32 + lane] = acc;
}

// ---------------- launch ----------------------------------------------------
extern "C" void kernel_launch(void* const* d_in, const int* in_sizes, int n_in,
                              void* d_out, int out_size)
{
    const int*   edge_rows = (const int*)  d_in[0];
    const int*   edge_cols = (const int*)  d_in[1];
    const float* edge_vals = (const float*)d_in[2];
    const float* h         = (const float*)d_in[3];
    const float* W         = (const float*)d_in[4];
    const float* b         = (const float*)d_in[5];
    float*       out       = (float*)d_out;

    const int n_edges = in_sizes[0];

    // 1) row_ptr (scatter) + W fragment prep
    {
        int threads = 256;
        int blocks  = (n_edges + threads - 1) / threads;
        rowptr_kernel<<<blocks, threads>>>(edge_rows, n_edges);
        wprep_kernel<<<16, 256>>>(W);
    }

    // 2) g = h @ W.T  (smem-staged fp16 tensor cores, fp32 accumulate)
    {
        int blocks = (N_NODES + MTILE - 1) / MTILE;   // 1563
        gemm_kernel<<<blocks, 128>>>(h);
    }

    // 3) SpMM + bias + relu
    {
        int warps_per_block = 8;             // 256 threads
        int blocks = (N_NODES + warps_per_block - 1) / warps_per_block;
        spmm_kernel<<<blocks, 256>>>(edge_cols, edge_vals, b, out);
    }
}

// round 11
// speedup vs baseline: 1.0550x; 1.0550x over previous
#include <cuda_runtime.h>
#include <cuda_bf16.h>
#include <cuda_fp16.h>
#include <cstdint>

#define N_NODES 100000
#define D 128

// ---------------- scratch (device globals: no allocations allowed) ----------
__device__ int    g_rowptr[N_NODES + 1];
__device__ __half g_hW[(size_t)N_NODES * D];   // h @ W.T in fp16, 25.6 MB
// Pre-swizzled W fragments for mma.sync m16n8k16 fp16.
// Index: ((kstep*16 + ntile)*32 + lane) -> uint2 {b0, b1}
__device__ uint2 g_Whf[8 * 16 * 32];

// ---------------- Kernel 1: row_ptr via scatter over sorted rows ------------
__global__ void rowptr_kernel(const int* __restrict__ rows, int n_edges) {
    int e = blockIdx.x * blockDim.x + threadIdx.x;
    if (e >= n_edges) return;
    int b = __ldg(&rows[e]);
    if (e == 0) {
        for (int i = 0; i <= b; i++) g_rowptr[i] = 0;
    } else {
        int a = __ldg(&rows[e - 1]);
        for (int i = a + 1; i <= b; i++) g_rowptr[i] = e;
    }
    if (e == n_edges - 1) {
        for (int i = b + 1; i <= N_NODES; i++) g_rowptr[i] = n_edges;
    }
}

// ---------------- Kernel 1b: W fragment prep (fp16) -------------------------
__device__ __forceinline__ uint32_t pack2_h16(float x, float y) {
    __half2 v = __floats2half2_rn(x, y);
    return *(uint32_t*)&v;
}

__global__ void wprep_kernel(const float* __restrict__ W) {
    int t = blockIdx.x * blockDim.x + threadIdx.x;   // 0..4095
    if (t >= 8 * 16 * 32) return;
    int lane  = t & 31;
    int ntile = (t >> 5) & 15;
    int kstep = t >> 9;

    int n  = ntile * 8 + (lane >> 2);
    int k0 = kstep * 16 + (lane & 3) * 2;

    float w00 = __ldg(&W[n * 128 + k0]);
    float w01 = __ldg(&W[n * 128 + k0 + 1]);
    float w10 = __ldg(&W[n * 128 + k0 + 8]);
    float w11 = __ldg(&W[n * 128 + k0 + 9]);

    uint2 f;
    f.x = pack2_h16(w00, w01);
    f.y = pack2_h16(w10, w11);
    g_Whf[t] = f;
}

// ---------------- Kernel 2: g = h @ W.T, smem-staged fp16 mma ----------------
// (unchanged from R10 — measured improvement)
#define MTILE 64
#define APAD  136

__device__ __forceinline__ void mma_f16(float* c, const uint32_t* a, uint2 b) {
    asm volatile(
        "mma.sync.aligned.m16n8k16.row.col.f32.f16.f16.f32 "
        "{%0,%1,%2,%3}, {%4,%5,%6,%7}, {%8,%9}, {%0,%1,%2,%3};"
        : "+f"(c[0]), "+f"(c[1]), "+f"(c[2]), "+f"(c[3])
        : "r"(a[0]), "r"(a[1]), "r"(a[2]), "r"(a[3]), "r"(b.x), "r"(b.y));
}

__global__ void __launch_bounds__(128, 4) gemm_kernel(
    const float* __restrict__ A)   // h [N_NODES, 128]
{
    __shared__ __half sA[MTILE * APAD];   // 17.4 KB

    const int tid    = threadIdx.x;
    const int lane   = tid & 31;
    const int warp   = tid >> 5;
    const int m_base = blockIdx.x * MTILE;

    #pragma unroll
    for (int q = 0; q < 16; q++) {
        int idx = q * 128 + tid;          // 0..2047
        int row = idx >> 5;
        int c4  = idx & 31;
        int rsrc = min(m_base + row, N_NODES - 1);
        float4 v = __ldg(&((const float4*)A)[(size_t)rsrc * 32 + c4]);
        __half2 p0 = __floats2half2_rn(v.x, v.y);
        __half2 p1 = __floats2half2_rn(v.z, v.w);
        *(__half2*)&sA[row * APAD + c4 * 4]     = p0;
        *(__half2*)&sA[row * APAD + c4 * 4 + 2] = p1;
    }
    __syncthreads();

    const int grp  = lane >> 2;
    const int quad = lane & 3;
    const int mrow = (warp >> 1) * 32;
    const int ntb  = (warp & 1) * 8;

    float acc[2][8][4];
    #pragma unroll
    for (int f = 0; f < 2; f++)
        #pragma unroll
        for (int nt = 0; nt < 8; nt++)
            #pragma unroll
            for (int i = 0; i < 4; i++) acc[f][nt][i] = 0.f;

    #pragma unroll
    for (int kstep = 0; kstep < 8; kstep++) {
        int kb = kstep * 16 + quad * 2;
        uint32_t a[2][4];
        #pragma unroll
        for (int f = 0; f < 2; f++) {
            int r = mrow + f * 16 + grp;
            a[f][0] = *(uint32_t*)&sA[r * APAD + kb];
            a[f][1] = *(uint32_t*)&sA[(r + 8) * APAD + kb];
            a[f][2] = *(uint32_t*)&sA[r * APAD + kb + 8];
            a[f][3] = *(uint32_t*)&sA[(r + 8) * APAD + kb + 8];
        }
        #pragma unroll
        for (int nt = 0; nt < 8; nt++) {
            uint2 wh = __ldg(&g_Whf[(kstep * 16 + ntb + nt) * 32 + lane]);
            mma_f16(acc[0][nt], a[0], wh);
            mma_f16(acc[1][nt], a[1], wh);
        }
    }
    __syncthreads();

    #pragma unroll
    for (int f = 0; f < 2; f++) {
        #pragma unroll
        for (int nt = 0; nt < 8; nt++) {
            int col = (ntb + nt) * 8 + quad * 2;
            int r0  = mrow + f * 16 + grp;
            *(__half2*)&sA[r0 * APAD + col] =
                __floats2half2_rn(acc[f][nt][0], acc[f][nt][1]);
            *(__half2*)&sA[(r0 + 8) * APAD + col] =
                __floats2half2_rn(acc[f][nt][2], acc[f][nt][3]);
        }
    }
    __syncthreads();

    #pragma unroll
    for (int q = 0; q < 8; q++) {
        int idx = q * 128 + tid;          // 0..1023
        int row = idx >> 4;
        int c16 = idx & 15;
        int rdst = m_base + row;
        if (rdst < N_NODES) {
            uint4 v = *(uint4*)&sA[row * APAD + c16 * 8];
            *(uint4*)&g_hW[(size_t)rdst * 128 + c16 * 8] = v;
        }
    }
}

// ---------------- Kernel 3: SpMM, half-warp per node, fp32 accum ------------
// Half-warp (16 lanes) per node; lane owns 8 features (uint4 = 16B fp16).
// Both halves run a uniform loop padded to the warp-max degree; invalid lanes
// carry v=0 (exact no-op). Per edge: 2 shfl(w16) + 1 LDG.128 + cvt + 8 FFMA,
// amortized over 2 nodes per warp.
__global__ void __launch_bounds__(256) spmm_kernel(
    const int*   __restrict__ cols,
    const float* __restrict__ vals,
    const float* __restrict__ bias,
    float*       __restrict__ out)
{
    const int warp_id = (blockIdx.x * blockDim.x + threadIdx.x) >> 5;
    const unsigned lane = threadIdx.x & 31;
    const unsigned hl   = lane & 15;          // lane within half-warp
    const int nid = warp_id * 2 + (int)(lane >> 4);
    if (warp_id * 2 >= N_NODES) return;

    int start = 0, end = 0;
    if (nid < N_NODES) {
        start = g_rowptr[nid];
        end   = g_rowptr[nid + 1];
    }
    const int deg = end - start;
    const int odeg = __shfl_xor_sync(0xffffffffu, deg, 16);
    const int ntrips = (max(deg, odeg) + 15) >> 4;

    const uint4* __restrict__ g4 = ((const uint4*)g_hW) + hl;   // row = 16 uint4

    float acc[8];
    #pragma unroll
    for (int i = 0; i < 8; i++) acc[i] = 0.f;

    for (int t = 0; t < ntrips; t++) {
        int e = start + t * 16 + (int)hl;
        int   c = 0; float v = 0.f;
        if (e < end) {
            c = __ldg(&cols[e]);
            v = __ldg(&vals[e]);
        }
        #pragma unroll
        for (int j = 0; j < 16; j++) {
            unsigned cj = (unsigned)__shfl_sync(0xffffffffu, c, j, 16);
            float    vj = __shfl_sync(0xffffffffu, v, j, 16);
            uint4 raw = __ldg(&g4[cj * 16u]);
            float2 f0 = __half22float2(*(__half2*)&raw.x);
            float2 f1 = __half22float2(*(__half2*)&raw.y);
            float2 f2 = __half22float2(*(__half2*)&raw.z);
            float2 f3 = __half22float2(*(__half2*)&raw.w);
            acc[0] = fmaf(vj, f0.x, acc[0]);
            acc[1] = fmaf(vj, f0.y, acc[1]);
            acc[2] = fmaf(vj, f1.x, acc[2]);
            acc[3] = fmaf(vj, f1.y, acc[3]);
            acc[4] = fmaf(vj, f2.x, acc[4]);
            acc[5] = fmaf(vj, f2.y, acc[5]);
            acc[6] = fmaf(vj, f3.x, acc[6]);
            acc[7] = fmaf(vj, f3.y, acc[7]);
        }
    }

    if (nid < N_NODES) {
        const float4* b4 = ((const float4*)bias) + hl * 2;
        float4 ba = __ldg(&b4[0]);
        float4 bb = __ldg(&b4[1]);
        float4 o0, o1;
        o0.x = fmaxf(acc[0] + ba.x, 0.f);
        o0.y = fmaxf(acc[1] + ba.y, 0.f);
        o0.z = fmaxf(acc[2] + ba.z, 0.f);
        o0.w = fmaxf(acc[3] + ba.w, 0.f);
        o1.x = fmaxf(acc[4] + bb.x, 0.f);
        o1.y = fmaxf(acc[5] + bb.y, 0.f);
        o1.z = fmaxf(acc[6] + bb.z, 0.f);
        o1.w = fmaxf(acc[7] + bb.w, 0.f);
        float4* orow = ((float4*)out) + (size_t)nid * 32 + hl * 2;
        orow[0] = o0;
        orow[1] = o1;
    }
}

// ---------------- launch ----------------------------------------------------
extern "C" void kernel_launch(void* const* d_in, const int* in_sizes, int n_in,
                              void* d_out, int out_size)
{
    const int*   edge_rows = (const int*)  d_in[0];
    const int*   edge_cols = (const int*)  d_in[1];
    const float* edge_vals = (const float*)d_in[2];
    const float* h         = (const float*)d_in[3];
    const float* W         = (const float*)d_in[4];
    const float* b         = (const float*)d_in[5];
    float*       out       = (float*)d_out;

    const int n_edges = in_sizes[0];

    // 1) row_ptr (scatter) + W fragment prep
    {
        int threads = 256;
        int blocks  = (n_edges + threads - 1) / threads;
        rowptr_kernel<<<blocks, threads>>>(edge_rows, n_edges);
        wprep_kernel<<<16, 256>>>(W);
    }

    // 2) g = h @ W.T  (smem-staged fp16 tensor cores, fp32 accumulate)
    {
        int blocks = (N_NODES + MTILE - 1) / MTILE;   // 1563
        gemm_kernel<<<blocks, 128>>>(h);
    }

    // 3) SpMM + bias + relu  (2 nodes per warp)
    {
        int nodes_per_block = 16;            // 8 warps x 2
        int blocks = (N_NODES + nodes_per_block - 1) / nodes_per_block;  // 6250
        spmm_kernel<<<blocks, 256>>>(edge_cols, edge_vals, b, out);
    }
}